// round 1
// baseline (speedup 1.0000x reference)
#include <cuda_runtime.h>
#include <math_constants.h>

#define B_ 4096
#define S_ 200
#define E_ 128
#define NT 256

#define KSTR 201  // keysT row stride (odd -> conflict-free both phases)

// shared-memory float offsets
#define OFF_KT   0
#define OFF_W1B  (128 * KSTR)            // 25728
#define OFF_W2   (OFF_W1B + 128 * 64)    // 33920
#define OFF_U    (OFF_W2 + 64 * 32)      // 35968
#define OFF_W3   (OFF_U + 64)            // 36032
#define OFF_B2   (OFF_W3 + 32)           // 36064
#define OFF_QS   (OFF_B2 + 32)           // 36096
#define OFF_SC   (OFF_QS + 128)          // 36224
#define OFF_RED  (OFF_SC + 256)          // 36480
#define OFF_PART (OFF_RED + 32)          // 36512
#define SMEM_FLOATS (OFF_PART + 256)     // 36768
#define SMEM_BYTES  (SMEM_FLOATS * 4)    // 147072

typedef unsigned long long ull;

__device__ __forceinline__ ull pk2(float lo, float hi) {
    ull r;
    asm("mov.b64 %0, {%1, %2};" : "=l"(r) : "f"(lo), "f"(hi));
    return r;
}
__device__ __forceinline__ void upk2(float& lo, float& hi, ull v) {
    asm("mov.b64 {%0, %1}, %2;" : "=f"(lo), "=f"(hi) : "l"(v));
}
__device__ __forceinline__ void fma2(ull& d, ull a, ull b) {
    asm("fma.rn.f32x2 %0, %1, %2, %0;" : "+l"(d) : "l"(a), "l"(b));
}

__global__ void __launch_bounds__(NT, 1)
attn_fused_kernel(const float* __restrict__ query,
                  const float* __restrict__ keys,
                  const int*   __restrict__ mask,
                  const float* __restrict__ W1,
                  const float* __restrict__ b1,
                  const float* __restrict__ W2,
                  const float* __restrict__ b2,
                  const float* __restrict__ W3,
                  const float* __restrict__ b3,
                  float* __restrict__ out)
{
    extern __shared__ float sm[];
    const int b = blockIdx.x;
    const int t = threadIdx.x;

    float* kT   = sm + OFF_KT;    // [128][KSTR]  keysT: kT[f*KSTR + s]
    float* W1b  = sm + OFF_W1B;   // [128][64]    key-half of W1
    float* W2s  = sm + OFF_W2;    // [64][32]
    float* us   = sm + OFF_U;     // [64]   u = W1a^T q + b1
    float* W3s  = sm + OFF_W3;    // [32]
    float* b2s  = sm + OFF_B2;    // [32]
    float* qs   = sm + OFF_QS;    // [128]
    float* sc   = sm + OFF_SC;    // scores -> weights
    float* red  = sm + OFF_RED;   // reductions
    float* part = sm + OFF_PART;  // attended partials

    // ---- Phase 0: stage inputs into shared memory ----
    const float* kg = keys + (size_t)b * (S_ * E_);
    for (int idx = t; idx < S_ * E_; idx += NT) {
        int s = idx >> 7;
        int f = idx & 127;
        kT[f * KSTR + s] = kg[idx];     // coalesced gmem, conflict-free STS
    }
    for (int idx = t; idx < 128 * 64; idx += NT) W1b[idx] = W1[128 * 64 + idx];
    for (int idx = t; idx < 64 * 32;  idx += NT) W2s[idx] = W2[idx];
    if (t < 32)              W3s[t]      = W3[t];
    if (t >= 32 && t < 64)   b2s[t - 32] = b2[t - 32];
    if (t < 128)             qs[t]       = query[(size_t)b * 128 + t];
    __syncthreads();

    // ---- Phase 0b: u[j] = b1[j] + sum_f q[f] * W1[f][j]  (query half, once per b) ----
    if (t < 64) {
        float a = b1[t];
        #pragma unroll 8
        for (int f = 0; f < 128; f++) a = fmaf(qs[f], W1[f * 64 + t], a);
        us[t] = a;
    }
    __syncthreads();

    // ---- Phase 1: per-token MLP -> score (thread t owns token s = t) ----
    float score = -CUDART_INF_F;
    if (t < S_) {
        // MLP1: h1 = relu(u + W1b^T kv), 32 packed f32x2 accumulators
        ull acc[32];
        #pragma unroll
        for (int j = 0; j < 32; j++) acc[j] = ((const ull*)us)[j];

        const float* kc = kT + t;
        #pragma unroll 4
        for (int f = 0; f < 128; f++) {
            float kv = kc[f * KSTR];
            ull kv2 = pk2(kv, kv);
            const ulonglong2* wr = (const ulonglong2*)(W1b + f * 64);
            #pragma unroll
            for (int q = 0; q < 16; q++) {
                ulonglong2 w = wr[q];          // LDS.128 broadcast, halves are f32x2 pairs
                fma2(acc[2 * q],     kv2, w.x);
                fma2(acc[2 * q + 1], kv2, w.y);
            }
        }
        float h1[64];
        #pragma unroll
        for (int j = 0; j < 32; j++) {
            float lo, hi; upk2(lo, hi, acc[j]);
            h1[2 * j]     = fmaxf(lo, 0.0f);
            h1[2 * j + 1] = fmaxf(hi, 0.0f);
        }

        // MLP2: h2 = relu(W2^T h1 + b2), 16 packed accumulators
        ull a2[16];
        #pragma unroll
        for (int g = 0; g < 16; g++) a2[g] = ((const ull*)b2s)[g];
        #pragma unroll 2
        for (int j = 0; j < 64; j++) {
            ull hd = pk2(h1[j], h1[j]);
            const ulonglong2* wr = (const ulonglong2*)(W2s + j * 32);
            #pragma unroll
            for (int q = 0; q < 8; q++) {
                ulonglong2 w = wr[q];
                fma2(a2[2 * q],     hd, w.x);
                fma2(a2[2 * q + 1], hd, w.y);
            }
        }

        // MLP3: score = b3 + W3^T relu(h2)
        float sacc = b3[0];
        #pragma unroll
        for (int p = 0; p < 16; p++) {
            float lo, hi; upk2(lo, hi, a2[p]);
            sacc = fmaf(fmaxf(lo, 0.0f), W3s[2 * p],     sacc);
            sacc = fmaf(fmaxf(hi, 0.0f), W3s[2 * p + 1], sacc);
        }
        if (mask[(size_t)b * S_ + t] == 0) sacc = -1e9f;
        score = sacc;
    }

    // ---- Phase 2: masked softmax over S (block-wide) ----
    float v = (t < S_) ? score : -CUDART_INF_F;
    #pragma unroll
    for (int o = 16; o > 0; o >>= 1) v = fmaxf(v, __shfl_xor_sync(0xffffffffu, v, o));
    if ((t & 31) == 0) red[t >> 5] = v;
    __syncthreads();
    if (t == 0) {
        float m = red[0];
        #pragma unroll
        for (int w = 1; w < 8; w++) m = fmaxf(m, red[w]);
        red[16] = m;
    }
    __syncthreads();
    const float mx = red[16];
    float p = (t < S_) ? __expf(score - mx) : 0.0f;
    v = p;
    #pragma unroll
    for (int o = 16; o > 0; o >>= 1) v += __shfl_xor_sync(0xffffffffu, v, o);
    if ((t & 31) == 0) red[t >> 5] = v;
    __syncthreads();
    if (t == 0) {
        float s = red[0];
        #pragma unroll
        for (int w = 1; w < 8; w++) s += red[w];
        red[17] = s;
    }
    __syncthreads();
    const float inv = 1.0f / red[17];
    const float wgt = p * inv;
    if (t < S_) {
        sc[t] = wgt;                                        // for attended phase
        out[(size_t)B_ * E_ + (size_t)b * S_ + t] = wgt;    // weights output
    }
    __syncthreads();

    // ---- Phase 3: attended[e] = sum_s keysT[e][s] * w[s] ----
    {
        const int e = t & 127;
        const int half = t >> 7;
        const float* kr = kT + e * KSTR + half * 100;
        const float* wp = sc + half * 100;
        float a = 0.0f;
        #pragma unroll 4
        for (int s = 0; s < 100; s++) a = fmaf(kr[s], wp[s], a);
        part[t] = a;
    }
    __syncthreads();
    if (t < 128) out[(size_t)b * E_ + t] = part[t] + part[t + 128];
}

extern "C" void kernel_launch(void* const* d_in, const int* in_sizes, int n_in,
                              void* d_out, int out_size) {
    const float* query = (const float*)d_in[0];
    const float* keys  = (const float*)d_in[1];
    const int*   mask  = (const int*)  d_in[2];
    const float* W1    = (const float*)d_in[3];
    const float* b1    = (const float*)d_in[4];
    const float* W2    = (const float*)d_in[5];
    const float* b2    = (const float*)d_in[6];
    const float* W3    = (const float*)d_in[7];
    const float* b3    = (const float*)d_in[8];
    float* out = (float*)d_out;

    cudaFuncSetAttribute(attn_fused_kernel,
                         cudaFuncAttributeMaxDynamicSharedMemorySize, SMEM_BYTES);
    attn_fused_kernel<<<B_, NT, SMEM_BYTES>>>(query, keys, mask,
                                              W1, b1, W2, b2, W3, b3, out);
}

// round 4
// speedup vs baseline: 1.3383x; 1.3383x over previous
#include <cuda_runtime.h>
#include <math_constants.h>
#include <cstdint>

#define B_ 4096
#define S_ 200
#define E_ 128
#define NT 256

#define CH   32          // f-chunk size
#define NCH  (E_ / CH)   // 4 chunks
#define CSTR 33          // chunk row stride (floats): banks (t+f)%32, conflict-free
#define CBUF (S_ * CSTR) // 6600 floats per buffer

// shared-memory float offsets
#define OFF_KC   0                       // 2 x 6600 = 13200
#define OFF_W1B  (2 * CBUF)              // 13200, 8192 floats
#define OFF_W2   (OFF_W1B + 128 * 64)    // 21392, 2048 floats
#define OFF_U    (OFF_W2 + 64 * 32)      // 23440
#define OFF_W3   (OFF_U + 64)            // 23504
#define OFF_B2   (OFF_W3 + 32)           // 23536
#define OFF_QS   (OFF_B2 + 32)           // 23568
#define OFF_SC   (OFF_QS + 128)          // 23696
#define OFF_RED  (OFF_SC + 256)          // 23952
#define OFF_PART (OFF_RED + 32)          // 23984
#define SMEM_FLOATS (OFF_PART + 256)     // 24240
#define SMEM_BYTES  (SMEM_FLOATS * 4)    // 96960 -> 2 CTAs/SM

typedef unsigned long long ull;

__device__ __forceinline__ ull pk2(float lo, float hi) {
    ull r;
    asm("mov.b64 %0, {%1, %2};" : "=l"(r) : "f"(lo), "f"(hi));
    return r;
}
__device__ __forceinline__ void upk2(float& lo, float& hi, ull v) {
    asm("mov.b64 {%0, %1}, %2;" : "=f"(lo), "=f"(hi) : "l"(v));
}
__device__ __forceinline__ void fma2(ull& d, ull a, ull b) {
    asm("fma.rn.f32x2 %0, %1, %2, %0;" : "+l"(d) : "l"(a), "l"(b));
}
__device__ __forceinline__ void cpa4(uint32_t dst, const float* src) {
    asm volatile("cp.async.ca.shared.global [%0], [%1], 4;" :: "r"(dst), "l"(src));
}
__device__ __forceinline__ void cpa_commit() {
    asm volatile("cp.async.commit_group;");
}
__device__ __forceinline__ void cpa_wait0() {
    asm volatile("cp.async.wait_group 0;");
}

__global__ void __launch_bounds__(NT, 2)
attn_fused_kernel(const float* __restrict__ query,
                  const float* __restrict__ keys,
                  const int*   __restrict__ mask,
                  const float* __restrict__ W1,
                  const float* __restrict__ b1,
                  const float* __restrict__ W2,
                  const float* __restrict__ b2,
                  const float* __restrict__ W3,
                  const float* __restrict__ b3,
                  float* __restrict__ out)
{
    extern __shared__ float sm[];
    const int b = blockIdx.x;
    const int t = threadIdx.x;

    float* kc   = sm + OFF_KC;    // [2][200][CSTR] keys chunk, double-buffered
    float* W1b  = sm + OFF_W1B;   // [128][64]  key-half of W1
    float* W2s  = sm + OFF_W2;    // [64][32]
    float* us   = sm + OFF_U;     // [64]
    float* W3s  = sm + OFF_W3;    // [32]
    float* b2s  = sm + OFF_B2;    // [32]
    float* qs   = sm + OFF_QS;    // [128]
    float* sc   = sm + OFF_SC;    // weights
    float* red  = sm + OFF_RED;   // reductions
    float* part = sm + OFF_PART;  // attended partials

    const float* kg = keys + (size_t)b * (S_ * E_);
    const uint32_t kc_base = (uint32_t)__cvta_generic_to_shared(kc);

    // ---- issue chunk 0 via cp.async (overlaps with weight staging below) ----
    {
        #pragma unroll
        for (int i = 0; i < (S_ * CH) / NT; i++) {       // 25 iters
            int idx = i * NT + t;
            int s = idx >> 5, f = idx & 31;
            cpa4(kc_base + (uint32_t)(s * CSTR + f) * 4, kg + s * E_ + f);
        }
        cpa_commit();
    }

    // ---- stage weights / small vectors ----
    for (int idx = t; idx < 128 * 64; idx += NT) W1b[idx] = W1[128 * 64 + idx];
    for (int idx = t; idx < 64 * 32;  idx += NT) W2s[idx] = W2[idx];
    if (t < 32)              W3s[t]      = W3[t];
    if (t >= 32 && t < 64)   b2s[t - 32] = b2[t - 32];
    if (t < 128)             qs[t]       = query[(size_t)b * 128 + t];
    __syncthreads();

    // ---- u[j] = b1[j] + sum_f q[f] * W1[f][j]  (query half, once per b) ----
    if (t < 64) {
        float a = b1[t];
        #pragma unroll 8
        for (int f = 0; f < 128; f++) a = fmaf(qs[f], W1[f * 64 + t], a);
        us[t] = a;
    }

    // ---- MLP1 over f-chunks, double-buffered ----
    ull acc[32];
    cpa_wait0();          // chunk 0 landed
    __syncthreads();      // also covers us[]

    #pragma unroll
    for (int j = 0; j < 32; j++) acc[j] = ((const ull*)us)[j];

    #pragma unroll
    for (int c = 0; c < NCH; c++) {
        // issue next chunk into the other buffer (its readers finished last iter)
        if (c + 1 < NCH) {
            const float* src = kg + (c + 1) * CH;
            uint32_t dstb = kc_base + (uint32_t)(((c + 1) & 1) * CBUF) * 4;
            #pragma unroll
            for (int i = 0; i < (S_ * CH) / NT; i++) {
                int idx = i * NT + t;
                int s = idx >> 5, f = idx & 31;
                cpa4(dstb + (uint32_t)(s * CSTR + f) * 4, src + s * E_ + f);
            }
            cpa_commit();
        }

        if (t < S_) {
            const float* kcc = kc + (c & 1) * CBUF + t * CSTR;
            const float* wb  = W1b + c * CH * 64;
            #pragma unroll 4
            for (int f = 0; f < CH; f++) {
                float kv = kcc[f];
                ull kv2 = pk2(kv, kv);
                const ulonglong2* wr = (const ulonglong2*)(wb + f * 64);
                #pragma unroll
                for (int q = 0; q < 16; q++) {
                    ulonglong2 w = wr[q];     // LDS.128 broadcast, halves are f32x2 pairs
                    fma2(acc[2 * q],     kv2, w.x);
                    fma2(acc[2 * q + 1], kv2, w.y);
                }
            }
        }

        if (c + 1 < NCH) {
            cpa_wait0();       // next chunk landed
        }
        __syncthreads();       // all reads of current buffer done before reuse
    }

    // ---- MLP2 / MLP3 -> score ----
    float score = -CUDART_INF_F;
    if (t < S_) {
        float h1[64];
        #pragma unroll
        for (int j = 0; j < 32; j++) {
            float lo, hi; upk2(lo, hi, acc[j]);
            h1[2 * j]     = fmaxf(lo, 0.0f);
            h1[2 * j + 1] = fmaxf(hi, 0.0f);
        }

        ull a2[16];
        #pragma unroll
        for (int g = 0; g < 16; g++) a2[g] = ((const ull*)b2s)[g];
        #pragma unroll 2
        for (int j = 0; j < 64; j++) {
            ull hd = pk2(h1[j], h1[j]);
            const ulonglong2* wr = (const ulonglong2*)(W2s + j * 32);
            #pragma unroll
            for (int q = 0; q < 8; q++) {
                ulonglong2 w = wr[q];
                fma2(a2[2 * q],     hd, w.x);
                fma2(a2[2 * q + 1], hd, w.y);
            }
        }

        float sacc = b3[0];
        #pragma unroll
        for (int p = 0; p < 16; p++) {
            float lo, hi; upk2(lo, hi, a2[p]);
            sacc = fmaf(fmaxf(lo, 0.0f), W3s[2 * p],     sacc);
            sacc = fmaf(fmaxf(hi, 0.0f), W3s[2 * p + 1], sacc);
        }
        if (mask[(size_t)b * S_ + t] == 0) sacc = -1e9f;
        score = sacc;
    }

    // ---- masked softmax over S (block-wide) ----
    float v = (t < S_) ? score : -CUDART_INF_F;
    #pragma unroll
    for (int o = 16; o > 0; o >>= 1) v = fmaxf(v, __shfl_xor_sync(0xffffffffu, v, o));
    if ((t & 31) == 0) red[t >> 5] = v;
    __syncthreads();
    if (t == 0) {
        float m = red[0];
        #pragma unroll
        for (int w = 1; w < 8; w++) m = fmaxf(m, red[w]);
        red[16] = m;
    }
    __syncthreads();
    const float mx = red[16];
    float p = (t < S_) ? __expf(score - mx) : 0.0f;
    v = p;
    #pragma unroll
    for (int o = 16; o > 0; o >>= 1) v += __shfl_xor_sync(0xffffffffu, v, o);
    if ((t & 31) == 0) red[t >> 5] = v;
    __syncthreads();
    if (t == 0) {
        float s = red[0];
        #pragma unroll
        for (int w = 1; w < 8; w++) s += red[w];
        red[17] = s;
    }
    __syncthreads();
    const float inv = 1.0f / red[17];
    const float wgt = p * inv;
    if (t < S_) {
        sc[t] = wgt;                                        // for attended phase
        out[(size_t)B_ * E_ + (size_t)b * S_ + t] = wgt;    // weights output
    }
    __syncthreads();

    // ---- attended[e] = sum_s keys[b][s][e] * w[s]  (gmem re-read, L2 hits) ----
    {
        const int e = t & 127;
        const int half = t >> 7;
        const float* kr = kg + (size_t)(half * 100) * E_ + e;
        const float* wp = sc + half * 100;
        float a0 = 0.0f, a1 = 0.0f, a2v = 0.0f, a3 = 0.0f;
        #pragma unroll 4
        for (int s = 0; s < 100; s += 4) {
            a0  = fmaf(kr[(s + 0) * E_], wp[s + 0], a0);
            a1  = fmaf(kr[(s + 1) * E_], wp[s + 1], a1);
            a2v = fmaf(kr[(s + 2) * E_], wp[s + 2], a2v);
            a3  = fmaf(kr[(s + 3) * E_], wp[s + 3], a3);
        }
        part[t] = (a0 + a1) + (a2v + a3);
    }
    __syncthreads();
    if (t < 128) out[(size_t)b * E_ + t] = part[t] + part[t + 128];
}

extern "C" void kernel_launch(void* const* d_in, const int* in_sizes, int n_in,
                              void* d_out, int out_size) {
    const float* query = (const float*)d_in[0];
    const float* keys  = (const float*)d_in[1];
    const int*   mask  = (const int*)  d_in[2];
    const float* W1    = (const float*)d_in[3];
    const float* b1    = (const float*)d_in[4];
    const float* W2    = (const float*)d_in[5];
    const float* b2    = (const float*)d_in[6];
    const float* W3    = (const float*)d_in[7];
    const float* b3    = (const float*)d_in[8];
    float* out = (float*)d_out;

    cudaFuncSetAttribute(attn_fused_kernel,
                         cudaFuncAttributeMaxDynamicSharedMemorySize, SMEM_BYTES);
    attn_fused_kernel<<<B_, NT, SMEM_BYTES>>>(query, keys, mask,
                                              W1, b1, W2, b2, W3, b3, out);
}

// round 7
// speedup vs baseline: 1.7580x; 1.3136x over previous
#include <cuda_runtime.h>
#include <math_constants.h>
#include <cstdint>

#define B_ 4096
#define S_ 200
#define E_ 128
#define NT 256

#define CH   32          // f-chunk size
#define NCH  (E_ / CH)   // 4 chunks
#define CSTR 33          // keys chunk row stride (floats), conflict-free
#define CBUF (S_ * CSTR) // 6600 floats per buffer

#define HSTR 65          // h1 row stride
#define GSTR 33          // h2 row stride

// shared-memory float offsets (region A and W1B are reused after MLP1)
#define OFF_A    0                       // kc: 2*6600=13200 ; later h1: 200*65=13000
#define OFF_W1B  13200                   // W1 key half: 8192 ; later h2: 200*33=6600
#define OFF_W2   (OFF_W1B + 8192)        // 21392, 2048 floats
#define OFF_U    (OFF_W2 + 2048)         // 23440, 64
#define OFF_W3   (OFF_U + 64)            // 23504, 32
#define OFF_B2   (OFF_W3 + 32)           // 23536, 32
#define OFF_QS   (OFF_B2 + 32)           // 23568, 128
#define OFF_SC   (OFF_QS + 128)          // 23696, 256
#define OFF_RED  (OFF_SC + 256)          // 23952, 32
#define OFF_PART (OFF_RED + 32)          // 23984, 256
#define SMEM_FLOATS (OFF_PART + 256)     // 24240
#define SMEM_BYTES  (SMEM_FLOATS * 4)    // 96960 -> 2 CTAs/SM

typedef unsigned long long ull;

__device__ __forceinline__ ull pk2(float lo, float hi) {
    ull r;
    asm("mov.b64 %0, {%1, %2};" : "=l"(r) : "f"(lo), "f"(hi));
    return r;
}
__device__ __forceinline__ void upk2(float& lo, float& hi, ull v) {
    asm("mov.b64 {%0, %1}, %2;" : "=f"(lo), "=f"(hi) : "l"(v));
}
__device__ __forceinline__ void fma2(ull& d, ull a, ull b) {
    asm("fma.rn.f32x2 %0, %1, %2, %0;" : "+l"(d) : "l"(a), "l"(b));
}
__device__ __forceinline__ void cpa4(uint32_t dst, const float* src) {
    asm volatile("cp.async.ca.shared.global [%0], [%1], 4;" :: "r"(dst), "l"(src));
}
__device__ __forceinline__ void cpa_commit() {
    asm volatile("cp.async.commit_group;");
}
__device__ __forceinline__ void cpa_wait0() {
    asm volatile("cp.async.wait_group 0;");
}

__global__ void __launch_bounds__(NT, 2)
attn_fused_kernel(const float* __restrict__ query,
                  const float* __restrict__ keys,
                  const int*   __restrict__ mask,
                  const float* __restrict__ W1,
                  const float* __restrict__ b1,
                  const float* __restrict__ W2,
                  const float* __restrict__ b2,
                  const float* __restrict__ W3,
                  const float* __restrict__ b3,
                  float* __restrict__ out)
{
    extern __shared__ float sm[];
    const int b = blockIdx.x;
    const int t = threadIdx.x;
    const int sg = t >> 2;   // token group: tokens 4sg..4sg+3 (sg < 50 active)
    const int jg = t & 3;    // j group: j in [16jg, 16jg+16)

    float* kc   = sm + OFF_A;     // [2][200][CSTR] keys chunks (double buffer)
    float* W1b  = sm + OFF_W1B;   // [128][64]
    float* W2s  = sm + OFF_W2;    // [64][32]
    float* us   = sm + OFF_U;     // [64]
    float* W3s  = sm + OFF_W3;    // [32]
    float* b2s  = sm + OFF_B2;    // [32]
    float* qs   = sm + OFF_QS;    // [128]
    float* sc   = sm + OFF_SC;    // weights
    float* red  = sm + OFF_RED;   // reductions
    float* part = sm + OFF_PART;  // attended partials

    const float* kg = keys + (size_t)b * (S_ * E_);
    const uint32_t kc_base = (uint32_t)__cvta_generic_to_shared(kc);

    // ---- issue chunk 0 via cp.async (overlaps with weight staging below) ----
    {
        #pragma unroll
        for (int i = 0; i < (S_ * CH) / NT; i++) {       // 25 iters
            int idx = i * NT + t;
            int s = idx >> 5, f = idx & 31;
            cpa4(kc_base + (uint32_t)(s * CSTR + f) * 4, kg + s * E_ + f);
        }
        cpa_commit();
    }

    // ---- stage weights / small vectors ----
    for (int idx = t; idx < 128 * 64; idx += NT) W1b[idx] = W1[128 * 64 + idx];
    for (int idx = t; idx < 64 * 32;  idx += NT) W2s[idx] = W2[idx];
    if (t < 32)              W3s[t]      = W3[t];
    if (t >= 32 && t < 64)   b2s[t - 32] = b2[t - 32];
    if (t < 128)             qs[t]       = query[(size_t)b * 128 + t];
    __syncthreads();

    // ---- u[j] = b1[j] + sum_f q[f] * W1[f][j]  (query half, once per b) ----
    if (t < 64) {
        float a = b1[t];
        #pragma unroll 8
        for (int f = 0; f < 128; f++) a = fmaf(qs[f], W1[f * 64 + t], a);
        us[t] = a;
    }

    // ---- MLP1: 4-token x 16-j register tile per thread, chunked + double-buffered ----
    ull acc[4][8];     // acc[i][p] = h1 pair (j = 16jg+2p, +1) for token 4sg+i
    cpa_wait0();       // chunk 0 landed
    __syncthreads();   // also covers us[]

    {
        const ull* usu = (const ull*)us;
        #pragma unroll
        for (int p = 0; p < 8; p++) {
            ull u0 = usu[jg * 8 + p];
            acc[0][p] = u0; acc[1][p] = u0; acc[2][p] = u0; acc[3][p] = u0;
        }
    }

    #pragma unroll
    for (int c = 0; c < NCH; c++) {
        // issue next chunk into the other buffer
        if (c + 1 < NCH) {
            const float* src = kg + (c + 1) * CH;
            uint32_t dstb = kc_base + (uint32_t)(((c + 1) & 1) * CBUF) * 4;
            #pragma unroll
            for (int i = 0; i < (S_ * CH) / NT; i++) {
                int idx = i * NT + t;
                int s = idx >> 5, f = idx & 31;
                cpa4(dstb + (uint32_t)(s * CSTR + f) * 4, src + s * E_ + f);
            }
            cpa_commit();
        }

        if (t < S_) {
            const float* r0 = kc + (c & 1) * CBUF + (4 * sg + 0) * CSTR;
            const float* r1 = r0 + CSTR;
            const float* r2 = r1 + CSTR;
            const float* r3 = r2 + CSTR;
            const float* wb = W1b + c * CH * 64 + jg * 16;
            #pragma unroll 2
            for (int f = 0; f < CH; f++) {
                ull kv2[4];
                kv2[0] = pk2(r0[f], r0[f]);
                kv2[1] = pk2(r1[f], r1[f]);
                kv2[2] = pk2(r2[f], r2[f]);
                kv2[3] = pk2(r3[f], r3[f]);
                const ulonglong2* wr = (const ulonglong2*)(wb + f * 64);
                ulonglong2 w0 = wr[0], w1 = wr[1], w2v = wr[2], w3v = wr[3];
                #pragma unroll
                for (int i = 0; i < 4; i++) {
                    fma2(acc[i][0], kv2[i], w0.x);  fma2(acc[i][1], kv2[i], w0.y);
                    fma2(acc[i][2], kv2[i], w1.x);  fma2(acc[i][3], kv2[i], w1.y);
                    fma2(acc[i][4], kv2[i], w2v.x); fma2(acc[i][5], kv2[i], w2v.y);
                    fma2(acc[i][6], kv2[i], w3v.x); fma2(acc[i][7], kv2[i], w3v.y);
                }
            }
        }

        if (c + 1 < NCH) cpa_wait0();
        __syncthreads();   // all reads of current buffer done before reuse
    }

    // ---- relu(h1) -> smem (reuses keys-chunk region, safe after the sync above) ----
    float* h1s = sm + OFF_A;   // [200][HSTR]
    if (t < S_) {
        #pragma unroll
        for (int i = 0; i < 4; i++) {
            float* row = h1s + (4 * sg + i) * HSTR + jg * 16;
            #pragma unroll
            for (int p = 0; p < 8; p++) {
                float lo, hi; upk2(lo, hi, acc[i][p]);
                row[2 * p]     = fmaxf(lo, 0.0f);
                row[2 * p + 1] = fmaxf(hi, 0.0f);
            }
        }
    }
    __syncthreads();

    // ---- MLP2: 4-token x 8-g register tile (gg = jg) ----
    ull a2[4][4];      // a2[i][q] = h2 pair (g = 8jg+2q, +1) for token 4sg+i
    {
        const ull* b2u = (const ull*)b2s;
        #pragma unroll
        for (int q = 0; q < 4; q++) {
            ull bq = b2u[jg * 4 + q];
            a2[0][q] = bq; a2[1][q] = bq; a2[2][q] = bq; a2[3][q] = bq;
        }
    }
    if (t < S_) {
        const float* h0 = h1s + (4 * sg + 0) * HSTR;
        const float* h1r = h0 + HSTR;
        const float* h2r = h1r + HSTR;
        const float* h3r = h2r + HSTR;
        const float* w2base = W2s + jg * 8;
        #pragma unroll 4
        for (int j = 0; j < 64; j++) {
            ull hd[4];
            hd[0] = pk2(h0[j],  h0[j]);
            hd[1] = pk2(h1r[j], h1r[j]);
            hd[2] = pk2(h2r[j], h2r[j]);
            hd[3] = pk2(h3r[j], h3r[j]);
            const ulonglong2* wr = (const ulonglong2*)(w2base + j * 32);
            ulonglong2 wa = wr[0], wb2 = wr[1];
            #pragma unroll
            for (int i = 0; i < 4; i++) {
                fma2(a2[i][0], hd[i], wa.x);  fma2(a2[i][1], hd[i], wa.y);
                fma2(a2[i][2], hd[i], wb2.x); fma2(a2[i][3], hd[i], wb2.y);
            }
        }
    }
    __syncthreads();   // W1b region reads done (MLP1) long ago; h2 alias safe

    // ---- relu(h2) -> smem (reuses W1b region) ----
    float* h2s = sm + OFF_W1B;   // [200][GSTR]
    if (t < S_) {
        #pragma unroll
        for (int i = 0; i < 4; i++) {
            float* row = h2s + (4 * sg + i) * GSTR + jg * 8;
            #pragma unroll
            for (int q = 0; q < 4; q++) {
                float lo, hi; upk2(lo, hi, a2[i][q]);
                row[2 * q]     = fmaxf(lo, 0.0f);
                row[2 * q + 1] = fmaxf(hi, 0.0f);
            }
        }
    }
    __syncthreads();

    // ---- MLP3: score per token (thread t owns token t) ----
    float score = -CUDART_INF_F;
    if (t < S_) {
        const float* row = h2s + t * GSTR;
        float sacc = b3[0];
        #pragma unroll
        for (int g = 0; g < 32; g++) sacc = fmaf(row[g], W3s[g], sacc);
        if (mask[(size_t)b * S_ + t] == 0) sacc = -1e9f;
        score = sacc;
    }

    // ---- masked softmax over S (block-wide) ----
    float v = (t < S_) ? score : -CUDART_INF_F;
    #pragma unroll
    for (int o = 16; o > 0; o >>= 1) v = fmaxf(v, __shfl_xor_sync(0xffffffffu, v, o));
    if ((t & 31) == 0) red[t >> 5] = v;
    __syncthreads();
    if (t == 0) {
        float m = red[0];
        #pragma unroll
        for (int w = 1; w < 8; w++) m = fmaxf(m, red[w]);
        red[16] = m;
    }
    __syncthreads();
    const float mx = red[16];
    float p = (t < S_) ? __expf(score - mx) : 0.0f;
    v = p;
    #pragma unroll
    for (int o = 16; o > 0; o >>= 1) v += __shfl_xor_sync(0xffffffffu, v, o);
    if ((t & 31) == 0) red[t >> 5] = v;
    __syncthreads();
    if (t == 0) {
        float s = red[0];
        #pragma unroll
        for (int w = 1; w < 8; w++) s += red[w];
        red[17] = s;
    }
    __syncthreads();
    const float inv = 1.0f / red[17];
    const float wgt = p * inv;
    if (t < S_) {
        sc[t] = wgt;                                        // for attended phase
        out[(size_t)B_ * E_ + (size_t)b * S_ + t] = wgt;    // weights output
    }
    __syncthreads();

    // ---- attended[e] = sum_s keys[b][s][e] * w[s]  (gmem re-read, L2 hits) ----
    {
        const int e = t & 127;
        const int half = t >> 7;
        const float* kr = kg + (size_t)(half * 100) * E_ + e;
        const float* wp = sc + half * 100;
        float a0 = 0.0f, a1 = 0.0f, a2v = 0.0f, a3 = 0.0f;
        #pragma unroll 4
        for (int s = 0; s < 100; s += 4) {
            a0  = fmaf(kr[(s + 0) * E_], wp[s + 0], a0);
            a1  = fmaf(kr[(s + 1) * E_], wp[s + 1], a1);
            a2v = fmaf(kr[(s + 2) * E_], wp[s + 2], a2v);
            a3  = fmaf(kr[(s + 3) * E_], wp[s + 3], a3);
        }
        part[t] = (a0 + a1) + (a2v + a3);
    }
    __syncthreads();
    if (t < 128) out[(size_t)b * E_ + t] = part[t] + part[t + 128];
}

extern "C" void kernel_launch(void* const* d_in, const int* in_sizes, int n_in,
                              void* d_out, int out_size) {
    const float* query = (const float*)d_in[0];
    const float* keys  = (const float*)d_in[1];
    const int*   mask  = (const int*)  d_in[2];
    const float* W1    = (const float*)d_in[3];
    const float* b1    = (const float*)d_in[4];
    const float* W2    = (const float*)d_in[5];
    const float* b2    = (const float*)d_in[6];
    const float* W3    = (const float*)d_in[7];
    const float* b3    = (const float*)d_in[8];
    float* out = (float*)d_out;

    cudaFuncSetAttribute(attn_fused_kernel,
                         cudaFuncAttributeMaxDynamicSharedMemorySize, SMEM_BYTES);
    attn_fused_kernel<<<B_, NT, SMEM_BYTES>>>(query, keys, mask,
                                              W1, b1, W2, b2, W3, b3, out);
}

// round 10
// speedup vs baseline: 1.9713x; 1.1213x over previous
#include <cuda_runtime.h>
#include <math_constants.h>
#include <cstdint>

#define B_ 4096
#define S_ 200
#define E_ 128
#define NT 256

#define CH   32            // f per chunk
#define NCH  (E_ / CH)     // 4 chunks
#define SROW 204           // transposed chunk row stride (mult of 4 for LDS.128)
#define CBUF (CH * SROW)   // 6528 floats per buffer

#define W1STR 68           // W1b row stride (64 + one 4-float mid-gap)
#define HSTR  68           // h1 row stride (mult of 4 for float4 stores)
#define GSTR  33           // h2 row stride

// shared-memory float offsets
#define OFF_A    0                        // kc: 2*6528=13056 ; later h1s (13600, spills into W1B) ; later h2s (6600)
#define OFF_W1B  13056                    // 128*68 = 8704
#define OFF_W2   (OFF_W1B + 8704)         // 21760, 2048
#define OFF_U    (OFF_W2 + 2048)          // 23808, 64
#define OFF_W3   (OFF_U + 64)             // 23872, 32
#define OFF_B2   (OFF_W3 + 32)            // 23904, 32
#define OFF_QS   (OFF_B2 + 32)            // 23936, 128
#define OFF_SC   (OFF_QS + 128)           // 24064, 256
#define OFF_RED  (OFF_SC + 256)           // 24320, 32
#define OFF_PART (OFF_RED + 32)           // 24352, 256
#define SMEM_FLOATS (OFF_PART + 256)      // 24608
#define SMEM_BYTES  (SMEM_FLOATS * 4)     // 98432 -> 2 CTAs/SM

typedef unsigned long long ull;

__device__ __forceinline__ ull pk2(float lo, float hi) {
    ull r;
    asm("mov.b64 %0, {%1, %2};" : "=l"(r) : "f"(lo), "f"(hi));
    return r;
}
__device__ __forceinline__ void upk2(float& lo, float& hi, ull v) {
    asm("mov.b64 {%0, %1}, %2;" : "=f"(lo), "=f"(hi) : "l"(v));
}
__device__ __forceinline__ void fma2(ull& d, ull a, ull b) {
    asm("fma.rn.f32x2 %0, %1, %2, %0;" : "+l"(d) : "l"(a), "l"(b));
}
__device__ __forceinline__ void cpa4(uint32_t dst, const float* src) {
    asm volatile("cp.async.ca.shared.global [%0], [%1], 4;" :: "r"(dst), "l"(src));
}
__device__ __forceinline__ void cpa_commit() {
    asm volatile("cp.async.commit_group;");
}
__device__ __forceinline__ void cpa_wait0() {
    asm volatile("cp.async.wait_group 0;");
}

__global__ void __launch_bounds__(NT, 2)
attn_fused_kernel(const float* __restrict__ query,
                  const float* __restrict__ keys,
                  const int*   __restrict__ mask,
                  const float* __restrict__ W1,
                  const float* __restrict__ b1,
                  const float* __restrict__ W2,
                  const float* __restrict__ b2,
                  const float* __restrict__ W3,
                  const float* __restrict__ b3,
                  float* __restrict__ out)
{
    extern __shared__ float sm[];
    const int b = blockIdx.x;
    const int t = threadIdx.x;

    float* kc   = sm + OFF_A;     // [2][CH][SROW] transposed keys chunks
    float* W1b  = sm + OFF_W1B;   // [128][W1STR] gapped
    float* W2s  = sm + OFF_W2;    // [64][32]
    float* us   = sm + OFF_U;     // [64]
    float* W3s  = sm + OFF_W3;    // [32]
    float* b2s  = sm + OFF_B2;    // [32]
    float* qs   = sm + OFF_QS;    // [128]
    float* sc   = sm + OFF_SC;    // weights
    float* red  = sm + OFF_RED;   // reductions
    float* part = sm + OFF_PART;  // attended partials

    const float* kg = keys + (size_t)b * (S_ * E_);
    const uint32_t kc_base = (uint32_t)__cvta_generic_to_shared(kc);

    // ---- transposed staging of chunk 0 via cp.async ----
    // lane mapping: 4 f x 8 s per warp-quarter -> STS bank-conflict-free
    {
        #pragma unroll
        for (int i = 0; i < (S_ * CH) / NT; i++) {       // 25 iters
            int idx = i * NT + t;
            int s_lo = idx & 7;
            int f_lo = (idx >> 3) & 3;
            int grp  = idx >> 5;
            int f    = f_lo + 4 * (grp & 7);
            int s    = s_lo + 8 * (grp >> 3);
            cpa4(kc_base + (uint32_t)(f * SROW + s) * 4, kg + s * E_ + f);
        }
        cpa_commit();
    }

    // ---- stage weights (W1b gapped: dst j-offset = j + ((j>>5)<<2)) ----
    for (int idx = t; idx < 128 * 64; idx += NT) {
        int f = idx >> 6, j = idx & 63;
        W1b[f * W1STR + j + ((j >> 5) << 2)] = W1[128 * 64 + idx];
    }
    for (int idx = t; idx < 64 * 32; idx += NT) W2s[idx] = W2[idx];
    if (t < 32)              W3s[t]      = W3[t];
    if (t >= 32 && t < 64)   b2s[t - 32] = b2[t - 32];
    if (t < 128)             qs[t]       = query[(size_t)b * 128 + t];
    __syncthreads();

    // ---- u[j] = b1[j] + sum_f q[f] * W1[f][j]  (query half) ----
    if (t < 64) {
        float a = b1[t];
        #pragma unroll 8
        for (int f = 0; f < 128; f++) a = fmaf(qs[f], W1[f * 64 + t], a);
        us[t] = a;
    }

    // ---- MLP1: 8-token x 8-j tile per thread (tg = t>>3 < 25, jg = t&7) ----
    const int tg = t >> 3;
    const int jg = t & 7;
    const int woff = jg * 8 + ((jg >> 2) << 2);   // gapped j-block offset

    ull acc[8][4];    // acc[tok][jp]: j-pair (8jg+2p, +1) for token 8tg+tok
    cpa_wait0();
    __syncthreads();  // chunk 0 + us ready

    {
        const ull* usu = (const ull*)us;
        ull u0 = usu[jg * 4 + 0], u1 = usu[jg * 4 + 1];
        ull u2 = usu[jg * 4 + 2], u3 = usu[jg * 4 + 3];
        #pragma unroll
        for (int tk = 0; tk < 8; tk++) {
            acc[tk][0] = u0; acc[tk][1] = u1; acc[tk][2] = u2; acc[tk][3] = u3;
        }
    }

    #pragma unroll
    for (int c = 0; c < NCH; c++) {
        if (c + 1 < NCH) {
            const float* src = kg + (c + 1) * CH;
            uint32_t dstb = kc_base + (uint32_t)(((c + 1) & 1) * CBUF) * 4;
            #pragma unroll
            for (int i = 0; i < (S_ * CH) / NT; i++) {
                int idx = i * NT + t;
                int s_lo = idx & 7;
                int f_lo = (idx >> 3) & 3;
                int grp  = idx >> 5;
                int f    = f_lo + 4 * (grp & 7);
                int s    = s_lo + 8 * (grp >> 3);
                cpa4(dstb + (uint32_t)(f * SROW + s) * 4, src + s * E_ + f);
            }
            cpa_commit();
        }

        if (t < S_) {
            const float* kr   = kc + (c & 1) * CBUF + 8 * tg;
            const float* wrow = W1b + (c * CH) * W1STR + woff;
            #pragma unroll 4
            for (int f = 0; f < CH; f++) {
                const float4 ka = *(const float4*)(kr + f * SROW);
                const float4 kb = *(const float4*)(kr + f * SROW + 4);
                ull k0 = pk2(ka.x, ka.x), k1 = pk2(ka.y, ka.y);
                ull k2 = pk2(ka.z, ka.z), k3 = pk2(ka.w, ka.w);
                ull k4 = pk2(kb.x, kb.x), k5 = pk2(kb.y, kb.y);
                ull k6 = pk2(kb.z, kb.z), k7 = pk2(kb.w, kb.w);
                const ulonglong2 wA = *(const ulonglong2*)(wrow + f * W1STR);
                const ulonglong2 wB = *(const ulonglong2*)(wrow + f * W1STR + 4);
                fma2(acc[0][0], k0, wA.x); fma2(acc[0][1], k0, wA.y);
                fma2(acc[0][2], k0, wB.x); fma2(acc[0][3], k0, wB.y);
                fma2(acc[1][0], k1, wA.x); fma2(acc[1][1], k1, wA.y);
                fma2(acc[1][2], k1, wB.x); fma2(acc[1][3], k1, wB.y);
                fma2(acc[2][0], k2, wA.x); fma2(acc[2][1], k2, wA.y);
                fma2(acc[2][2], k2, wB.x); fma2(acc[2][3], k2, wB.y);
                fma2(acc[3][0], k3, wA.x); fma2(acc[3][1], k3, wA.y);
                fma2(acc[3][2], k3, wB.x); fma2(acc[3][3], k3, wB.y);
                fma2(acc[4][0], k4, wA.x); fma2(acc[4][1], k4, wA.y);
                fma2(acc[4][2], k4, wB.x); fma2(acc[4][3], k4, wB.y);
                fma2(acc[5][0], k5, wA.x); fma2(acc[5][1], k5, wA.y);
                fma2(acc[5][2], k5, wB.x); fma2(acc[5][3], k5, wB.y);
                fma2(acc[6][0], k6, wA.x); fma2(acc[6][1], k6, wA.y);
                fma2(acc[6][2], k6, wB.x); fma2(acc[6][3], k6, wB.y);
                fma2(acc[7][0], k7, wA.x); fma2(acc[7][1], k7, wA.y);
                fma2(acc[7][2], k7, wB.x); fma2(acc[7][3], k7, wB.y);
            }
        }

        if (c + 1 < NCH) cpa_wait0();
        __syncthreads();
    }

    // ---- relu(h1) -> smem [200][HSTR] at OFF_A (kc + W1b head are dead) ----
    float* h1s = sm + OFF_A;
    if (t < S_) {
        #pragma unroll
        for (int i = 0; i < 8; i++) {
            float* row = h1s + (8 * tg + i) * HSTR + 8 * jg;
            float v0, v1, v2, v3, v4, v5, v6, v7;
            upk2(v0, v1, acc[i][0]); upk2(v2, v3, acc[i][1]);
            upk2(v4, v5, acc[i][2]); upk2(v6, v7, acc[i][3]);
            *(float4*)(row)     = make_float4(fmaxf(v0, 0.f), fmaxf(v1, 0.f),
                                              fmaxf(v2, 0.f), fmaxf(v3, 0.f));
            *(float4*)(row + 4) = make_float4(fmaxf(v4, 0.f), fmaxf(v5, 0.f),
                                              fmaxf(v6, 0.f), fmaxf(v7, 0.f));
        }
    }
    __syncthreads();

    // ---- MLP2: 4 tokens (stride 50) x 8 g per thread (sg2 = t>>2, jg2 = t&3) ----
    const int sg2 = t >> 2;
    const int jg2 = t & 3;
    ull a2[4][4];
    {
        const ull* b2u = (const ull*)b2s;
        ull q0 = b2u[jg2 * 4 + 0], q1 = b2u[jg2 * 4 + 1];
        ull q2 = b2u[jg2 * 4 + 2], q3 = b2u[jg2 * 4 + 3];
        #pragma unroll
        for (int i = 0; i < 4; i++) {
            a2[i][0] = q0; a2[i][1] = q1; a2[i][2] = q2; a2[i][3] = q3;
        }
    }
    if (t < S_) {
        const float* h0  = h1s + sg2 * HSTR;
        const float* h1r = h1s + (sg2 + 50) * HSTR;
        const float* h2r = h1s + (sg2 + 100) * HSTR;
        const float* h3r = h1s + (sg2 + 150) * HSTR;
        const float* w2base = W2s + jg2 * 8;
        #pragma unroll 4
        for (int j = 0; j < 64; j++) {
            ull hd0 = pk2(h0[j],  h0[j]);
            ull hd1 = pk2(h1r[j], h1r[j]);
            ull hd2 = pk2(h2r[j], h2r[j]);
            ull hd3 = pk2(h3r[j], h3r[j]);
            const ulonglong2* wr = (const ulonglong2*)(w2base + j * 32);
            ulonglong2 wa = wr[0], wb2 = wr[1];
            fma2(a2[0][0], hd0, wa.x); fma2(a2[0][1], hd0, wa.y);
            fma2(a2[0][2], hd0, wb2.x); fma2(a2[0][3], hd0, wb2.y);
            fma2(a2[1][0], hd1, wa.x); fma2(a2[1][1], hd1, wa.y);
            fma2(a2[1][2], hd1, wb2.x); fma2(a2[1][3], hd1, wb2.y);
            fma2(a2[2][0], hd2, wa.x); fma2(a2[2][1], hd2, wa.y);
            fma2(a2[2][2], hd2, wb2.x); fma2(a2[2][3], hd2, wb2.y);
            fma2(a2[3][0], hd3, wa.x); fma2(a2[3][1], hd3, wa.y);
            fma2(a2[3][2], hd3, wb2.x); fma2(a2[3][3], hd3, wb2.y);
        }
    }
    __syncthreads();   // h1 reads done before h2 overwrites OFF_A

    // ---- relu(h2) -> smem [200][GSTR] at OFF_A ----
    float* h2s = sm + OFF_A;
    if (t < S_) {
        #pragma unroll
        for (int i = 0; i < 4; i++) {
            float* row = h2s + (sg2 + 50 * i) * GSTR + jg2 * 8;
            #pragma unroll
            for (int q = 0; q < 4; q++) {
                float lo, hi; upk2(lo, hi, a2[i][q]);
                row[2 * q]     = fmaxf(lo, 0.0f);
                row[2 * q + 1] = fmaxf(hi, 0.0f);
            }
        }
    }
    __syncthreads();

    // ---- MLP3: score per token ----
    float score = -CUDART_INF_F;
    if (t < S_) {
        const float* row = h2s + t * GSTR;
        float sacc = b3[0];
        #pragma unroll
        for (int g = 0; g < 32; g++) sacc = fmaf(row[g], W3s[g], sacc);
        if (mask[(size_t)b * S_ + t] == 0) sacc = -1e9f;
        score = sacc;
    }

    // ---- masked softmax over S ----
    float v = (t < S_) ? score : -CUDART_INF_F;
    #pragma unroll
    for (int o = 16; o > 0; o >>= 1) v = fmaxf(v, __shfl_xor_sync(0xffffffffu, v, o));
    if ((t & 31) == 0) red[t >> 5] = v;
    __syncthreads();
    if (t == 0) {
        float m = red[0];
        #pragma unroll
        for (int w = 1; w < 8; w++) m = fmaxf(m, red[w]);
        red[16] = m;
    }
    __syncthreads();
    const float mx = red[16];
    float p = (t < S_) ? __expf(score - mx) : 0.0f;
    v = p;
    #pragma unroll
    for (int o = 16; o > 0; o >>= 1) v += __shfl_xor_sync(0xffffffffu, v, o);
    if ((t & 31) == 0) red[t >> 5] = v;
    __syncthreads();
    if (t == 0) {
        float s = red[0];
        #pragma unroll
        for (int w = 1; w < 8; w++) s += red[w];
        red[17] = s;
    }
    __syncthreads();
    const float inv = 1.0f / red[17];
    const float wgt = p * inv;
    if (t < S_) {
        sc[t] = wgt;
        out[(size_t)B_ * E_ + (size_t)b * S_ + t] = wgt;
    }
    __syncthreads();

    // ---- attended[e] = sum_s keys[b][s][e] * w[s] (gmem re-read, L2 hits) ----
    {
        const int e = t & 127;
        const int half = t >> 7;
        const float* kr = kg + (size_t)(half * 100) * E_ + e;
        const float* wp = sc + half * 100;
        float a0 = 0.0f, a1 = 0.0f, a2v = 0.0f, a3 = 0.0f;
        #pragma unroll 4
        for (int s = 0; s < 100; s += 4) {
            a0  = fmaf(kr[(s + 0) * E_], wp[s + 0], a0);
            a1  = fmaf(kr[(s + 1) * E_], wp[s + 1], a1);
            a2v = fmaf(kr[(s + 2) * E_], wp[s + 2], a2v);
            a3  = fmaf(kr[(s + 3) * E_], wp[s + 3], a3);
        }
        part[t] = (a0 + a1) + (a2v + a3);
    }
    __syncthreads();
    if (t < 128) out[(size_t)b * E_ + t] = part[t] + part[t + 128];
}

extern "C" void kernel_launch(void* const* d_in, const int* in_sizes, int n_in,
                              void* d_out, int out_size) {
    const float* query = (const float*)d_in[0];
    const float* keys  = (const float*)d_in[1];
    const int*   mask  = (const int*)  d_in[2];
    const float* W1    = (const float*)d_in[3];
    const float* b1    = (const float*)d_in[4];
    const float* W2    = (const float*)d_in[5];
    const float* b2    = (const float*)d_in[6];
    const float* W3    = (const float*)d_in[7];
    const float* b3    = (const float*)d_in[8];
    float* out = (float*)d_out;

    cudaFuncSetAttribute(attn_fused_kernel,
                         cudaFuncAttributeMaxDynamicSharedMemorySize, SMEM_BYTES);
    attn_fused_kernel<<<B_, NT, SMEM_BYTES>>>(query, keys, mask,
                                              W1, b1, W2, b2, W3, b3, out);
}